// round 17
// baseline (speedup 1.0000x reference)
#include <cuda_runtime.h>
#include <cuda_fp16.h>
#include <cstdint>
#include <math.h>

// ---------------- problem constants ----------------
#define NB     2
#define TT     2048
#define BT     4096      // NB*TT tokens
#define DM     2048
#define NH     16
#define DH     128
#define CH     144       // NH + DH
#define RQ     6
#define RKV    4
#define NQ     864       // RQ*CH
#define NKV    576       // RKV*CH

// ---------------- scratch (device globals; no allocs allowed) ----------------
__device__ float g_abq [BT * NQ];
__device__ float g_abkv[BT * NKV];

// single fp16 everything
__device__ __half g_x16 [BT * DM];
__device__ __half g_wq16[NQ * DM];
__device__ __half g_wkv16[NKV * DM];
__device__ __half g_wo16[DM * DM];
__device__ __half g_y16 [BT * DM];

#define QKV_ELEMS (NB * NH * TT * DH)
__device__ __half g_q16[QKV_ELEMS];
__device__ __half g_k16[QKV_ELEMS];
__device__ __half g_v16[QKV_ELEMS];

// ================= helpers =================
__device__ __forceinline__ uint32_t smem_u32(const void* p) {
    uint32_t a;
    asm("{ .reg .u64 t; cvta.to.shared.u64 t, %1; cvt.u32.u64 %0, t; }" : "=r"(a) : "l"(p));
    return a;
}
#define SWZ(o)  ((o) ^ (((o) >> 3) & 0x70))   // 128B-row swizzle (GEMM tiles)
#define ASW(o)  ((o) ^ (((o) >> 4) & 0x70))   // 256B-row swizzle (attn tiles)

__device__ __forceinline__ void ldsm4(uint32_t* r, uint32_t addr) {
    asm volatile("ldmatrix.sync.aligned.m8n8.x4.shared.b16 {%0,%1,%2,%3}, [%4];"
        : "=r"(r[0]), "=r"(r[1]), "=r"(r[2]), "=r"(r[3]) : "r"(addr));
}
__device__ __forceinline__ void ldsm4t(uint32_t* r, uint32_t addr) {
    asm volatile("ldmatrix.sync.aligned.m8n8.x4.trans.shared.b16 {%0,%1,%2,%3}, [%4];"
        : "=r"(r[0]), "=r"(r[1]), "=r"(r[2]), "=r"(r[3]) : "r"(addr));
}
__device__ __forceinline__ void mma_f16(float* c, const uint32_t* a, const uint32_t* b) {
    asm volatile("mma.sync.aligned.m16n8k16.row.col.f32.f16.f16.f32 "
        "{%0,%1,%2,%3}, {%4,%5,%6,%7}, {%8,%9}, {%0,%1,%2,%3};"
        : "+f"(c[0]), "+f"(c[1]), "+f"(c[2]), "+f"(c[3])
        : "r"(a[0]), "r"(a[1]), "r"(a[2]), "r"(a[3]), "r"(b[0]), "r"(b[1]));
}
#define CP_ASYNC(dst, src, sz) \
    asm volatile("cp.async.cg.shared.global [%0], [%1], 16, %2;" \
        :: "r"(dst), "l"(src), "r"(sz) : "memory")
#define CP_COMMIT() asm volatile("cp.async.commit_group;" ::: "memory")
#define CP_WAIT(n)  asm volatile("cp.async.wait_group %0;" :: "n"(n) : "memory")

__device__ __forceinline__ uint32_t pack_h2(__half lo, __half hi) {
    __half2 t; t.x = lo; t.y = hi;
    return *reinterpret_cast<uint32_t*>(&t);
}

// ======================================================================
// fused fp32 -> fp16 conversion of all four tensors (one launch)
// ======================================================================
__global__ __launch_bounds__(256) void conv_all(
    const float* __restrict__ s0, __half* __restrict__ h0, int n0,
    const float* __restrict__ s1, __half* __restrict__ h1, int n1,
    const float* __restrict__ s2, __half* __restrict__ h2, int n2,
    const float* __restrict__ s3, __half* __restrict__ h3, int n3)
{
    int i = blockIdx.x * 256 + threadIdx.x;
    if (i < n0)                     { h0[i] = __float2half(s0[i]); }
    else if (i < n0 + n1)           { int j = i - n0;           h1[j] = __float2half(s1[j]); }
    else if (i < n0 + n1 + n2)      { int j = i - n0 - n1;      h2[j] = __float2half(s2[j]); }
    else if (i < n0 + n1 + n2 + n3) { int j = i - n0 - n1 - n2; h3[j] = __float2half(s3[j]); }
}

// ======================================================================
// single-pass fp16 NT GEMM: C[M,N] = A[M,K] * B[N,K]^T
// 128x128 tile, 128 threads (4 warps, warp tile 64x64), 2-stage,
// 32KB/stage. N arbitrary (guarded).
// ======================================================================
#define GBM      128
#define GBN      128
#define OA_ST    16384                 // 128 x 64 fp16
#define OB_ST    16384                 // 128 x 64 fp16
#define OSTAGE   (OA_ST + OB_ST)       // 32KB
#define GEMM_SMEM (2 * OSTAGE + 1024)

__device__ __forceinline__ void gemm16_body(
    const __half* __restrict__ A, const __half* __restrict__ B,
    float* __restrict__ C, int N, int K, int bm, int bn, uint32_t smem)
{
    const int tid  = threadIdx.x;
    const int wid  = tid >> 5, lane = tid & 31;
    const int wm   = (wid >> 1) * 64;
    const int wn   = (wid & 1) * 64;
    const int nchunk = K >> 6;

    auto load_chunk = [&](int c, int buf) {
        const uint32_t base = smem + buf * OSTAGE;
        const int k0 = c * 64;
#pragma unroll
        for (int u = tid; u < 1024; u += 128) {
            int row = u >> 3, seg = u & 7;
            uint32_t so = SWZ((uint32_t)(row * 128 + seg * 16));
            CP_ASYNC(base + so, A + (size_t)(bm + row) * K + k0 + seg * 8, 16);
        }
#pragma unroll
        for (int u = tid; u < 1024; u += 128) {
            int row = u >> 3, seg = u & 7;
            uint32_t so = SWZ((uint32_t)(row * 128 + seg * 16));
            int n = bn + row;
            int sz = (n < N) ? 16 : 0;
            CP_ASYNC(base + OA_ST + so, B + (size_t)(n < N ? n : 0) * K + k0 + seg * 8, sz);
        }
        CP_COMMIT();
    };

    float acc[4][8][4];
#pragma unroll
    for (int i = 0; i < 4; i++)
#pragma unroll
        for (int j = 0; j < 8; j++)
#pragma unroll
            for (int q = 0; q < 4; q++) acc[i][j][q] = 0.f;

    load_chunk(0, 0);

    for (int c = 0; c < nchunk; c++) {
        const int buf = c & 1;
        if (c + 1 < nchunk) {
            load_chunk(c + 1, buf ^ 1);
            CP_WAIT(1);
        } else {
            CP_WAIT(0);
        }
        __syncthreads();

        const uint32_t sa  = smem + buf * OSTAGE;
        const uint32_t sbb = sa + OA_ST;

#pragma unroll
        for (int ks = 0; ks < 4; ks++) {
            const int kk = ks * 16;
            uint32_t ah[4][4], bh[4][4];
            {
                int r = lane & 15, ck = lane >> 4;
#pragma unroll
                for (int mt = 0; mt < 4; mt++) {
                    uint32_t off = SWZ((uint32_t)((wm + mt * 16 + r) * 128 + (kk + ck * 8) * 2));
                    ldsm4(ah[mt], sa + off);
                }
            }
            {
                int grp = lane >> 3, ln = lane & 7;
#pragma unroll
                for (int np = 0; np < 4; np++) {
                    int n = wn + np * 16 + (grp >> 1) * 8 + ln;
                    int kc = kk + (grp & 1) * 8;
                    uint32_t off = SWZ((uint32_t)(n * 128 + kc * 2));
                    ldsm4(bh[np], sbb + off);
                }
            }
#pragma unroll
            for (int mt = 0; mt < 4; mt++)
#pragma unroll
                for (int nt = 0; nt < 8; nt++)
                    mma_f16(acc[mt][nt], ah[mt], &bh[nt >> 1][(nt & 1) * 2]);
        }
        __syncthreads();
    }

#pragma unroll
    for (int mt = 0; mt < 4; mt++) {
        int r0 = bm + wm + mt * 16 + (lane >> 2);
#pragma unroll
        for (int nt = 0; nt < 8; nt++) {
            int col = bn + wn + nt * 8 + (lane & 3) * 2;
            if (col < N) {
                float* c0 = C + (size_t)r0 * N + col;
                float* c1 = C + (size_t)(r0 + 8) * N + col;
                c0[0] = acc[mt][nt][0]; c0[1] = acc[mt][nt][1];
                c1[0] = acc[mt][nt][2]; c1[1] = acc[mt][nt][3];
            }
        }
    }
}

#define QTILES  7                               // ceil(864/128)
#define KVTILES 5                               // ceil(576/128)
__global__ __launch_bounds__(128) void gemm_qkv(const __half* __restrict__ A)
{
    extern __shared__ char smraw[];
    const uint32_t smem0 = smem_u32(smraw);
    const uint32_t smem  = (smem0 + 1023) & ~1023u;
    const int bx = blockIdx.x;
    if (bx < QTILES)
        gemm16_body(A, g_wq16, g_abq, NQ, DM, blockIdx.y * GBM, bx * GBN, smem);
    else
        gemm16_body(A, g_wkv16, g_abkv, NKV, DM, blockIdx.y * GBM, (bx - QTILES) * GBN, smem);
}

__global__ __launch_bounds__(128) void gemm_out(
    const __half* __restrict__ A, const __half* __restrict__ B, float* __restrict__ C)
{
    extern __shared__ char smraw[];
    const uint32_t smem0 = smem_u32(smraw);
    const uint32_t smem  = (smem0 + 1023) & ~1023u;
    gemm16_body(A, B, C, DM, DM, blockIdx.y * GBM, blockIdx.x * GBN, smem);
}

// ======================================================================
// qkv: rank contraction + rotary (fp32 trig) -> single fp16 q,k,v [b,h,t,d]
// ======================================================================
__global__ __launch_bounds__(128) void qkv_kernel()
{
    const int m = blockIdx.x;
    const int b = m >> 11;
    const int t = m & (TT - 1);
    const int d = threadIdx.x;

    __shared__ float aq  [RQ][16];
    __shared__ float bq  [RQ][128];
    __shared__ float akv [RKV][16];
    __shared__ float braw[RKV][128];
    __shared__ float brot[RKV][128];

    const float* abq = g_abq + (size_t)m * NQ;
    for (int idx = d; idx < NQ; idx += 128) {
        int r = idx / CH, c = idx - r * CH;
        float v = abq[idx];
        if (c < 16) aq[r][c] = v; else bq[r][c - 16] = v;
    }
    const float* abkv = g_abkv + (size_t)m * NKV;
    for (int idx = d; idx < NKV; idx += 128) {
        int r = idx / CH, c = idx - r * CH;
        float v = abkv[idx];
        if (c < 16) akv[r][c] = v; else braw[r][c - 16] = v;
    }
    __syncthreads();

    {
        int j = d & 63;
        float inv = powf(1e-4f, (float)j * (1.f / 64.f));
        float sv, cv;
        sincosf((float)t * inv, &sv, &cv);
#pragma unroll
        for (int r = 0; r < RKV; r++) {
            float x1 = braw[r][j], x2 = braw[r][j + 64];
            brot[r][d] = (d < 64) ? (x1 * cv + x2 * sv) : (-x1 * sv + x2 * cv);
        }
    }

    const size_t base = (((size_t)b * NH) * TT + t) * DH + d;
#pragma unroll
    for (int h = 0; h < NH; h++) {
        float qv = 0.f;
#pragma unroll
        for (int r = 0; r < RQ; r++) qv += aq[r][h] * bq[r][d];
        qv *= (1.f / 6.f);
        float kv = (akv[0][h] * brot[0][d] + akv[1][h] * brot[1][d]) * 0.5f;
        float vv = (akv[2][h] * brot[2][d] + akv[3][h] * brot[3][d]) * 0.5f;
        size_t o = base + (size_t)h * TT * DH;
        g_q16[o] = __float2half(qv);
        g_k16[o] = __float2half(kv);
        g_v16[o] = __float2half(vv);
    }
}

// ======================================================================
// flash attention, causal, single-pass fp16 mma.sync (R16 winner).
// 128 threads (4 warps x 16 q-rows = 64-row Q tile), 32-row KV stages,
// 2-stage double buffer. smem 49KB -> 3 CTAs/SM.
// ======================================================================
#define ATTN_SMEM (49152 + 1024)

__global__ __launch_bounds__(128, 3) void attn_mma()
{
    extern __shared__ char smraw[];
    const uint32_t sb0 = smem_u32(smraw);
    const uint32_t sb = (sb0 + 1023) & ~1023u;

    const int tid = threadIdx.x, wid = tid >> 5, lane = tid & 31;
    const int qt = (int)gridDim.x - 1 - (int)blockIdx.x;   // heavy tiles first
    const int h = blockIdx.y, b = blockIdx.z;
    const size_t bh = ((size_t)b * NH + h) * TT;
    const int nkt = 2 * qt + 2;                            // 32-row kv tiles

    const uint32_t sQ = sb;

    {
        const char* qp = (const char*)g_q16 + (bh + (size_t)qt * 64) * 256;
        for (int u = tid; u < 1024; u += 128) {
            int row = u >> 4, seg = u & 15;
            uint32_t off = ASW((uint32_t)(row * 256 + seg * 16));
            CP_ASYNC(sQ + off, qp + row * 256 + seg * 16, 16);
        }
    }
    auto load_kv = [&](int kt, int s) {
        uint32_t base = sb + 16384 + (uint32_t)s * 16384;
        const char* kp = (const char*)g_k16 + (bh + (size_t)kt * 32) * 256;
        const char* vp = (const char*)g_v16 + (bh + (size_t)kt * 32) * 256;
        for (int u = tid; u < 512; u += 128) {
            int row = u >> 4, seg = u & 15;
            uint32_t off = ASW((uint32_t)(row * 256 + seg * 16));
            int go = row * 256 + seg * 16;
            CP_ASYNC(base + off,        kp + go, 16);
            CP_ASYNC(base + 8192 + off, vp + go, 16);
        }
        CP_COMMIT();
    };
    load_kv(0, 0);
    if (nkt > 1) load_kv(1, 1);

    float oacc[16][4];
#pragma unroll
    for (int dt = 0; dt < 16; dt++)
#pragma unroll
        for (int e = 0; e < 4; e++) oacc[dt][e] = 0.f;
    float rM0 = -1e30f, rM1 = -1e30f, rL0 = 0.f, rL1 = 0.f;

    const float scale = 0.08838834764831845f;
    const int r0g = qt * 64 + wid * 16 + (lane >> 2);

    for (int kt = 0; kt < nkt; kt++) {
        const int s = kt & 1;
        if (kt + 1 < nkt) { CP_WAIT(1); } else { CP_WAIT(0); }
        __syncthreads();
        const uint32_t base = sb + 16384 + (uint32_t)s * 16384;
        const uint32_t sK = base, sV = base + 8192;

        float sacc[4][4];
#pragma unroll
        for (int nt = 0; nt < 4; nt++)
#pragma unroll
            for (int e = 0; e < 4; e++) sacc[nt][e] = 0.f;

#pragma unroll
        for (int ks = 0; ks < 8; ks++) {
            uint32_t ah[4];
            {
                int r = lane & 15, ck = lane >> 4;
                uint32_t off = ASW((uint32_t)((wid * 16 + r) * 256 + (ks * 16 + ck * 8) * 2));
                ldsm4(ah, sQ + off);
            }
            uint32_t bh4[2][4];
            {
                int grp = lane >> 3, ln = lane & 7;
#pragma unroll
                for (int ng = 0; ng < 2; ng++) {
                    int n = ng * 16 + (grp >> 1) * 8 + ln;
                    int kc = ks * 16 + (grp & 1) * 8;
                    uint32_t off = ASW((uint32_t)(n * 256 + kc * 2));
                    ldsm4(bh4[ng], sK + off);
                }
            }
#pragma unroll
            for (int ng = 0; ng < 2; ng++) {
                mma_f16(sacc[ng * 2],     ah, bh4[ng]);
                mma_f16(sacc[ng * 2 + 1], ah, bh4[ng] + 2);
            }
        }

        const bool domask = (kt >= 2 * qt);
        float mx0 = -1e30f, mx1 = -1e30f;
#pragma unroll
        for (int nt = 0; nt < 4; nt++) {
            int c0 = kt * 32 + nt * 8 + (lane & 3) * 2;
#pragma unroll
            for (int e = 0; e < 4; e++) {
                float v = sacc[nt][e] * scale;
                if (domask) {
                    int cc = c0 + (e & 1);
                    int rr = r0g + ((e >> 1) << 3);
                    if (cc > rr) v = -1e30f;
                }
                sacc[nt][e] = v;
            }
            mx0 = fmaxf(mx0, fmaxf(sacc[nt][0], sacc[nt][1]));
            mx1 = fmaxf(mx1, fmaxf(sacc[nt][2], sacc[nt][3]));
        }
        mx0 = fmaxf(mx0, __shfl_xor_sync(0xffffffffu, mx0, 1));
        mx0 = fmaxf(mx0, __shfl_xor_sync(0xffffffffu, mx0, 2));
        mx1 = fmaxf(mx1, __shfl_xor_sync(0xffffffffu, mx1, 1));
        mx1 = fmaxf(mx1, __shfl_xor_sync(0xffffffffu, mx1, 2));

        float nM0 = fmaxf(rM0, mx0), nM1 = fmaxf(rM1, mx1);
        float cor0 = __expf(rM0 - nM0), cor1 = __expf(rM1 - nM1);
        rM0 = nM0; rM1 = nM1;

        float sum0 = 0.f, sum1 = 0.f;
        uint32_t pH01[4], pH23[4];
#pragma unroll
        for (int nt = 0; nt < 4; nt++) {
            float p0 = __expf(sacc[nt][0] - nM0);
            float p1 = __expf(sacc[nt][1] - nM0);
            float p2 = __expf(sacc[nt][2] - nM1);
            float p3 = __expf(sacc[nt][3] - nM1);
            sum0 += p0 + p1; sum1 += p2 + p3;
            pH01[nt] = pack_h2(__float2half(p0), __float2half(p1));
            pH23[nt] = pack_h2(__float2half(p2), __float2half(p3));
        }
        sum0 += __shfl_xor_sync(0xffffffffu, sum0, 1);
        sum0 += __shfl_xor_sync(0xffffffffu, sum0, 2);
        sum1 += __shfl_xor_sync(0xffffffffu, sum1, 1);
        sum1 += __shfl_xor_sync(0xffffffffu, sum1, 2);
        rL0 = rL0 * cor0 + sum0;
        rL1 = rL1 * cor1 + sum1;

#pragma unroll
        for (int dt = 0; dt < 16; dt++) {
            oacc[dt][0] *= cor0; oacc[dt][1] *= cor0;
            oacc[dt][2] *= cor1; oacc[dt][3] *= cor1;
        }

#pragma unroll
        for (int k2 = 0; k2 < 2; k2++) {
            uint32_t aH[4] = {pH01[2 * k2], pH23[2 * k2], pH01[2 * k2 + 1], pH23[2 * k2 + 1]};
            int krow = k2 * 16 + ((lane >> 3) & 1) * 8 + (lane & 7);
#pragma unroll
            for (int dh2 = 0; dh2 < 2; dh2++) {
                uint32_t vh4[4][4];
#pragma unroll
                for (int dq = 0; dq < 4; dq++) {
                    int dcol = (dh2 * 4 + dq) * 16 + (lane >> 4) * 8;
                    uint32_t off = ASW((uint32_t)(krow * 256 + dcol * 2));
                    ldsm4t(vh4[dq], sV + off);
                }
#pragma unroll
                for (int dq = 0; dq < 4; dq++) {
                    int dg = dh2 * 4 + dq;
                    mma_f16(oacc[dg * 2],     aH, vh4[dq]);
                    mma_f16(oacc[dg * 2 + 1], aH, vh4[dq] + 2);
                }
            }
        }
        __syncthreads();
        if (kt + 2 < nkt) load_kv(kt + 2, s);
    }

    // ---- normalize + store single-fp16 y ----
    float il0 = 1.f / rL0, il1 = 1.f / rL1;
    size_t row0 = ((size_t)b * TT + r0g) * DM + h * DH;
    size_t row1 = row0 + (size_t)8 * DM;
#pragma unroll
    for (int dt = 0; dt < 16; dt++) {
        int c = dt * 8 + (lane & 3) * 2;
        *(uint32_t*)(g_y16 + row0 + c) = pack_h2(__float2half(oacc[dt][0] * il0),
                                                 __float2half(oacc[dt][1] * il0));
        *(uint32_t*)(g_y16 + row1 + c) = pack_h2(__float2half(oacc[dt][2] * il1),
                                                 __float2half(oacc[dt][3] * il1));
    }
}

// ======================================================================
extern "C" void kernel_launch(void* const* d_in, const int* in_sizes, int n_in,
                              void* d_out, int out_size)
{
    const float* x   = (const float*)d_in[0];
    const float* Wq  = (const float*)d_in[1];
    const float* Wkv = (const float*)d_in[2];
    const float* Wo  = (const float*)d_in[3];
    float* out = (float*)d_out;

    __half *x16, *wq16, *wkv16, *wo16, *y16;
    cudaGetSymbolAddress((void**)&x16,   g_x16);
    cudaGetSymbolAddress((void**)&wq16,  g_wq16);
    cudaGetSymbolAddress((void**)&wkv16, g_wkv16);
    cudaGetSymbolAddress((void**)&wo16,  g_wo16);
    cudaGetSymbolAddress((void**)&y16,   g_y16);

    cudaFuncSetAttribute(gemm_qkv, cudaFuncAttributeMaxDynamicSharedMemorySize, GEMM_SMEM);
    cudaFuncSetAttribute(gemm_out, cudaFuncAttributeMaxDynamicSharedMemorySize, GEMM_SMEM);
    cudaFuncSetAttribute(attn_mma, cudaFuncAttributeMaxDynamicSharedMemorySize, ATTN_SMEM);

    // 0) fp32 -> fp16 conversions (one launch)
    {
        int n0 = BT * DM, n1 = NQ * DM, n2 = NKV * DM, n3 = DM * DM;
        conv_all<<<(n0 + n1 + n2 + n3 + 255) / 256, 256>>>(
            x, x16, n0, Wq, wq16, n1, Wkv, wkv16, n2, Wo, wo16, n3);
    }
    // 1) fused ab_q / ab_kv projections (128x128 tiles, 384 CTAs)
    {
        dim3 g(QTILES + KVTILES, BT / GBM);
        gemm_qkv<<<g, 128, GEMM_SMEM>>>(x16);
    }
    // 2) q,k,v (+rotary) -> single fp16
    qkv_kernel<<<BT, 128>>>();
    // 3) causal attention (single-pass fp16, 3 CTAs/SM) -> y16
    {
        dim3 g(TT / 64, NH, NB);
        attn_mma<<<g, 128, ATTN_SMEM>>>();
    }
    // 4) out = y16 @ Wo16^T (128x128 tiles, 512 CTAs)
    {
        dim3 g(DM / GBN, BT / GBM);
        gemm_out<<<g, 128, GEMM_SMEM>>>(y16, wo16, out);
    }
}